// round 2
// baseline (speedup 1.0000x reference)
#include <cuda_runtime.h>

// Problem constants
#define BB 4
#define SS 2048
#define DD 1024
#define PP 1024

// GEMM tile config
#define BM 128
#define BN 128
#define BK 8
#define TM 8
#define TN 8
#define NTHREADS 256   // (BM/TM)*(BN/TN)

// Scratch: q,k,v (B,S,P) fp32 = 32MB each; scores (B,S,S) fp32 = 64MB
__device__ float g_q[(long long)BB * SS * PP];
__device__ float g_k[(long long)BB * SS * PP];
__device__ float g_v[(long long)BB * SS * PP];
__device__ float g_s[(long long)BB * SS * SS];

// ---------------------------------------------------------------------------
// C = A(MxK, row-major) * B(KxN, row-major), batched via blockIdx.z strides.
// If causal_k != 0, the K loop is limited to kend = min(K, m0 + BM): used for
// context = P @ v where P[s,t] = 0 for t > s (softmax zeroes the diag-block tail).
// ---------------------------------------------------------------------------
__global__ __launch_bounds__(NTHREADS) void sgemm_nn(
    const float* __restrict__ A, const float* __restrict__ B, float* __restrict__ C,
    int M, int N, int K, int lda, int ldb, int ldc,
    long long strideA, long long strideB, long long strideC, int causal_k)
{
    __shared__ float As[BK][BM];
    __shared__ float Bs[BK][BN];

    const int bz = blockIdx.z;
    A += (long long)bz * strideA;
    B += (long long)bz * strideB;
    C += (long long)bz * strideC;

    const int m0 = blockIdx.y * BM;
    const int n0 = blockIdx.x * BN;
    const int tid = threadIdx.x;

    int kend = K;
    if (causal_k) { int lim = m0 + BM; kend = (lim < K) ? lim : K; }

    // A tile loader: 128 rows x 8 k, one float4 per thread along k
    const int arow = tid >> 1;
    const int acol = (tid & 1) << 2;
    // B tile loader: 8 rows(k) x 128 cols(n), one float4 per thread along n
    const int brow = tid >> 5;
    const int bcol = (tid & 31) << 2;

    const int ty = tid >> 4;   // 0..15
    const int tx = tid & 15;   // 0..15

    float acc[TM][TN];
#pragma unroll
    for (int i = 0; i < TM; i++)
#pragma unroll
        for (int j = 0; j < TN; j++) acc[i][j] = 0.f;

    for (int k0 = 0; k0 < kend; k0 += BK) {
        float4 a = *reinterpret_cast<const float4*>(
            &A[(long long)(m0 + arow) * lda + k0 + acol]);
        As[acol + 0][arow] = a.x;
        As[acol + 1][arow] = a.y;
        As[acol + 2][arow] = a.z;
        As[acol + 3][arow] = a.w;

        float4 b = *reinterpret_cast<const float4*>(
            &B[(long long)(k0 + brow) * ldb + n0 + bcol]);
        *reinterpret_cast<float4*>(&Bs[brow][bcol]) = b;

        __syncthreads();
#pragma unroll
        for (int kk = 0; kk < BK; kk++) {
            float af[TM], bf[TN];
            *reinterpret_cast<float4*>(&af[0]) = *reinterpret_cast<const float4*>(&As[kk][ty * TM]);
            *reinterpret_cast<float4*>(&af[4]) = *reinterpret_cast<const float4*>(&As[kk][ty * TM + 4]);
            *reinterpret_cast<float4*>(&bf[0]) = *reinterpret_cast<const float4*>(&Bs[kk][tx * TN]);
            *reinterpret_cast<float4*>(&bf[4]) = *reinterpret_cast<const float4*>(&Bs[kk][tx * TN + 4]);
#pragma unroll
            for (int i = 0; i < TM; i++)
#pragma unroll
                for (int j = 0; j < TN; j++)
                    acc[i][j] += af[i] * bf[j];
        }
        __syncthreads();
    }

#pragma unroll
    for (int i = 0; i < TM; i++) {
        long long row = m0 + ty * TM + i;
        float4* cp = reinterpret_cast<float4*>(&C[row * ldc + n0 + tx * TN]);
        cp[0] = make_float4(acc[i][0], acc[i][1], acc[i][2], acc[i][3]);
        cp[1] = make_float4(acc[i][4], acc[i][5], acc[i][6], acc[i][7]);
    }
}

// ---------------------------------------------------------------------------
// C = A(MxK, row-major) * B^T where B is (NxK, row-major). Used for scores.
// If causal != 0, blocks entirely above the diagonal (n0 > m0) are skipped —
// the softmax never reads those entries.
// ---------------------------------------------------------------------------
__global__ __launch_bounds__(NTHREADS) void sgemm_nt(
    const float* __restrict__ A, const float* __restrict__ B, float* __restrict__ C,
    int M, int N, int K, int lda, int ldb, int ldc,
    long long strideA, long long strideB, long long strideC, int causal)
{
    __shared__ float As[BK][BM];
    __shared__ float Bs[BK][BN];

    const int m0 = blockIdx.y * BM;
    const int n0 = blockIdx.x * BN;
    if (causal && n0 > m0) return;   // fully-masked tile

    const int bz = blockIdx.z;
    A += (long long)bz * strideA;
    B += (long long)bz * strideB;
    C += (long long)bz * strideC;

    const int tid = threadIdx.x;

    const int arow = tid >> 1;
    const int acol = (tid & 1) << 2;
    const int nrow = tid >> 1;
    const int kcol = (tid & 1) << 2;

    const int ty = tid >> 4;
    const int tx = tid & 15;

    float acc[TM][TN];
#pragma unroll
    for (int i = 0; i < TM; i++)
#pragma unroll
        for (int j = 0; j < TN; j++) acc[i][j] = 0.f;

    for (int k0 = 0; k0 < K; k0 += BK) {
        float4 a = *reinterpret_cast<const float4*>(
            &A[(long long)(m0 + arow) * lda + k0 + acol]);
        As[acol + 0][arow] = a.x;
        As[acol + 1][arow] = a.y;
        As[acol + 2][arow] = a.z;
        As[acol + 3][arow] = a.w;

        float4 b = *reinterpret_cast<const float4*>(
            &B[(long long)(n0 + nrow) * ldb + k0 + kcol]);
        Bs[kcol + 0][nrow] = b.x;
        Bs[kcol + 1][nrow] = b.y;
        Bs[kcol + 2][nrow] = b.z;
        Bs[kcol + 3][nrow] = b.w;

        __syncthreads();
#pragma unroll
        for (int kk = 0; kk < BK; kk++) {
            float af[TM], bf[TN];
            *reinterpret_cast<float4*>(&af[0]) = *reinterpret_cast<const float4*>(&As[kk][ty * TM]);
            *reinterpret_cast<float4*>(&af[4]) = *reinterpret_cast<const float4*>(&As[kk][ty * TM + 4]);
            *reinterpret_cast<float4*>(&bf[0]) = *reinterpret_cast<const float4*>(&Bs[kk][tx * TN]);
            *reinterpret_cast<float4*>(&bf[4]) = *reinterpret_cast<const float4*>(&Bs[kk][tx * TN + 4]);
#pragma unroll
            for (int i = 0; i < TM; i++)
#pragma unroll
                for (int j = 0; j < TN; j++)
                    acc[i][j] += af[i] * bf[j];
        }
        __syncthreads();
    }

#pragma unroll
    for (int i = 0; i < TM; i++) {
        long long row = m0 + ty * TM + i;
        float4* cp = reinterpret_cast<float4*>(&C[row * ldc + n0 + tx * TN]);
        cp[0] = make_float4(acc[i][0], acc[i][1], acc[i][2], acc[i][3]);
        cp[1] = make_float4(acc[i][4], acc[i][5], acc[i][6], acc[i][7]);
    }
}

// ---------------------------------------------------------------------------
// Causal softmax over each row of scores (in place), with 1/sqrt(P) scaling.
// Also zeroes entries t in (s, row_block_end) so the context GEMM can bound
// its K loop at the 128-row block boundary.
// ---------------------------------------------------------------------------
__global__ __launch_bounds__(256) void softmax_causal(float* __restrict__ Sc, int S, float scale)
{
    const int r = blockIdx.x;          // 0..B*S-1
    const int b = r / S;
    const int s = r % S;
    float* row = Sc + (long long)b * S * S + (long long)s * S;
    const int L = s + 1;
    const int tid = threadIdx.x;
    __shared__ float red[256];

    float mx = -1e30f;
    for (int i = tid; i < L; i += 256) mx = fmaxf(mx, row[i]);
    red[tid] = mx;
    __syncthreads();
    for (int o = 128; o > 0; o >>= 1) {
        if (tid < o) red[tid] = fmaxf(red[tid], red[tid + o]);
        __syncthreads();
    }
    mx = red[0] * scale;
    __syncthreads();

    float sum = 0.f;
    for (int i = tid; i < L; i += 256) {
        float e = __expf(row[i] * scale - mx);
        row[i] = e;
        sum += e;
    }
    red[tid] = sum;
    __syncthreads();
    for (int o = 128; o > 0; o >>= 1) {
        if (tid < o) red[tid] += red[tid + o];
        __syncthreads();
    }
    const float inv = 1.f / red[0];

    const int Lpad = ((L + 127) / 128) * 128;   // row-block end (= (s/128)*128 + 128)
    for (int i = tid; i < Lpad; i += 256) {
        if (i < L) row[i] *= inv;
        else       row[i] = 0.f;
    }
}

extern "C" void kernel_launch(void* const* d_in, const int* in_sizes, int n_in,
                              void* d_out, int out_size)
{
    const float* x  = (const float*)d_in[0];
    const float* Wq = (const float*)d_in[1];
    const float* Wk = (const float*)d_in[2];
    const float* Wv = (const float*)d_in[3];
    float* out = (float*)d_out;

    float *q, *k, *v, *sc;
    cudaGetSymbolAddress((void**)&q,  g_q);
    cudaGetSymbolAddress((void**)&k,  g_k);
    cudaGetSymbolAddress((void**)&v,  g_v);
    cudaGetSymbolAddress((void**)&sc, g_s);

    const long long sSP = (long long)SS * PP;
    const long long sSSq = (long long)SS * SS;

    dim3 tb(NTHREADS);

    // QKV projections: (B*S, D) @ (D, P)
    dim3 gproj(PP / BN, (BB * SS) / BM, 1);
    sgemm_nn<<<gproj, tb>>>(x, Wq, q, BB * SS, PP, DD, DD, PP, PP, 0, 0, 0, 0);
    sgemm_nn<<<gproj, tb>>>(x, Wk, k, BB * SS, PP, DD, DD, PP, PP, 0, 0, 0, 0);
    sgemm_nn<<<gproj, tb>>>(x, Wv, v, BB * SS, PP, DD, DD, PP, PP, 0, 0, 0, 0);

    // scores = q @ k^T per batch, skipping fully-masked upper tiles
    dim3 gs(SS / BN, SS / BM, BB);
    sgemm_nt<<<gs, tb>>>(q, k, sc, SS, SS, PP, PP, PP, SS, sSP, sSP, sSSq, 1);

    // causal softmax with 1/32 scaling
    softmax_causal<<<BB * SS, 256>>>(sc, SS, 0.03125f);

    // context = P @ v per batch, K loop bounded at row-block diagonal
    dim3 gc(PP / BN, SS / BM, BB);
    sgemm_nn<<<gc, tb>>>(sc, v, out, SS, PP, SS, SS, PP, PP, sSSq, sSP, sSP, 1);
}

// round 5
// speedup vs baseline: 3.4438x; 3.4438x over previous
#include <cuda_runtime.h>
#include <cstdint>

#define BB 4
#define SS 2048
#define DD 1024
#define PP 1024

// ---------------- scratch (device globals; no allocation allowed) ----------
__device__ float g_q[(size_t)BB * SS * PP];            // (B*S, P)
__device__ float g_k[(size_t)BB * SS * PP];            // (B*S, P)
__device__ float g_v[(size_t)BB * SS * PP];            // (B*S, P)
__device__ float g_s[(size_t)BB * SS * SS];            // per-batch (S, S)

// ---------------- helpers ---------------------------------------------------
__device__ __forceinline__ uint32_t smem_u32(const void* p) {
    uint32_t a;
    asm("{ .reg .u64 t; cvta.to.shared.u64 t, %1; cvt.u32.u64 %0, t; }"
        : "=r"(a) : "l"(p));
    return a;
}

__device__ __forceinline__ uint32_t f2tf32(float x) {
    uint32_t r;
    asm("cvt.rna.tf32.f32 %0, %1;" : "=r"(r) : "f"(x));
    return r;
}

#define CP_ASYNC16(dst_u32, src_ptr) \
    asm volatile("cp.async.cg.shared.global [%0], [%1], 16;" \
                 :: "r"(dst_u32), "l"(src_ptr) : "memory")
#define CP_COMMIT() asm volatile("cp.async.commit_group;" ::: "memory")
#define CP_WAIT(n)  asm volatile("cp.async.wait_group %0;" :: "n"(n) : "memory")

__device__ __forceinline__ void mma_tf32(float* c, const uint32_t* a, const uint32_t* b) {
    asm volatile(
        "mma.sync.aligned.m16n8k8.row.col.f32.tf32.tf32.f32 "
        "{%0,%1,%2,%3}, {%4,%5,%6,%7}, {%8,%9}, {%0,%1,%2,%3};"
        : "+f"(c[0]), "+f"(c[1]), "+f"(c[2]), "+f"(c[3])
        : "r"(a[0]), "r"(a[1]), "r"(a[2]), "r"(a[3]), "r"(b[0]), "r"(b[1]));
}

// ---------------- tf32 mma.sync GEMM ----------------------------------------
// C[m,n] = sum_k A[m,k] * B_eff[k,n]
//   BT=1 : B stored [N,K] row-major (NT, scores)   BT=0 : B stored [K,N] (NN)
// MODE: 0 plain | 1 causal tile-skip (n0>m0) | 2 K bounded at m0+128
//
// CTA: 128x128 tile, BK=32, 256 threads (8 warps, 4x2), warp tile 32x64.
#define BK 32
#define ASZ 18432            // 128 * 36 * 4 bytes  (pad 36)
#define BSZ_NT 18432         // 128 * 36 * 4
#define BSZ_NN 17408         // 32 * 136 * 4       (pad 136)
#define SMEM_TOTAL 73728     // 2*ASZ + 2*max(BSZ)

template <int BT, int MODE>
__global__ void __launch_bounds__(256, 2) gemm_tc(
    const float* __restrict__ A, const float* __restrict__ B, float* __restrict__ C,
    int lda, int ldb, int ldc, int K,
    long long sA, long long sB, long long sC)
{
    const int m0 = blockIdx.y * 128;
    const int n0 = blockIdx.x * 128;
    if (MODE == 1 && n0 > m0) return;

    extern __shared__ char smem[];
    const int bz = blockIdx.z;
    A += (long long)bz * sA;
    B += (long long)bz * sB;
    C += (long long)bz * sC;

    const int tid = threadIdx.x;
    const int lane = tid & 31;
    const int wid = tid >> 5;
    const int warp_m = wid & 3;      // 0..3  (32 rows each)
    const int warp_n = wid >> 2;     // 0..1  (64 cols each)

    const int BSZ = BT ? BSZ_NT : BSZ_NN;
    float* smA = reinterpret_cast<float*>(smem);
    float* smB = reinterpret_cast<float*>(smem + 2 * ASZ);
    const uint32_t smA_u = smem_u32(smA);
    const uint32_t smB_u = smem_u32(smB);

    int kend = K;
    if (MODE == 2) { int lim = m0 + 128; kend = (lim < K) ? lim : K; }
    const int T = kend / BK;

    float acc[2][8][4];
#pragma unroll
    for (int mt = 0; mt < 2; mt++)
#pragma unroll
        for (int nt = 0; nt < 8; nt++)
#pragma unroll
            for (int i = 0; i < 4; i++) acc[mt][nt][i] = 0.f;

    // ---- tile loader (cp.async, 4 float4 per thread per operand) ----
    auto load_tile = [&](int kt) {
        const int k0 = kt * BK;
        const int buf = kt & 1;
        const uint32_t dA = smA_u + buf * ASZ;
        const uint32_t dB = smB_u + buf * BSZ;
#pragma unroll
        for (int i = 0; i < 4; i++) {
            int slot = tid + i * 256;           // 0..1023
            int row = slot >> 3, c4 = slot & 7; // A / B-NT addressing
            const float* srcA = &A[(long long)(m0 + row) * lda + k0 + c4 * 4];
            CP_ASYNC16(dA + (uint32_t)(row * 36 + c4 * 4) * 4u, srcA);
            if (BT) {
                const float* srcB = &B[(long long)(n0 + row) * ldb + k0 + c4 * 4];
                CP_ASYNC16(dB + (uint32_t)(row * 36 + c4 * 4) * 4u, srcB);
            } else {
                int krow = slot >> 5, cc = slot & 31;
                const float* srcB = &B[(long long)(k0 + krow) * ldb + n0 + cc * 4];
                CP_ASYNC16(dB + (uint32_t)(krow * 136 + cc * 4) * 4u, srcB);
            }
        }
        CP_COMMIT();
    };

    load_tile(0);

    const int r0 = warp_m * 32 + (lane >> 2);
    const int cq = lane & 3;

    for (int kt = 0; kt < T; kt++) {
        if (kt + 1 < T) { load_tile(kt + 1); CP_WAIT(1); }
        else            { CP_WAIT(0); }
        __syncthreads();

        const float* bufA = smA + (kt & 1) * (ASZ / 4);
        const float* bufB = smB + (kt & 1) * (BSZ / 4);

#pragma unroll
        for (int ks = 0; ks < BK; ks += 8) {
            uint32_t a[2][4];
#pragma unroll
            for (int mt = 0; mt < 2; mt++) {
                int r = r0 + mt * 16;
                int c = ks + cq;
                a[mt][0] = f2tf32(bufA[r * 36 + c]);
                a[mt][1] = f2tf32(bufA[(r + 8) * 36 + c]);
                a[mt][2] = f2tf32(bufA[r * 36 + c + 4]);
                a[mt][3] = f2tf32(bufA[(r + 8) * 36 + c + 4]);
            }
            uint32_t b[8][2];
#pragma unroll
            for (int nt = 0; nt < 8; nt++) {
                int nb = warp_n * 64 + nt * 8 + (lane >> 2);
                if (BT) {
                    int c = ks + cq;
                    b[nt][0] = f2tf32(bufB[nb * 36 + c]);
                    b[nt][1] = f2tf32(bufB[nb * 36 + c + 4]);
                } else {
                    int kb = ks + cq;
                    b[nt][0] = f2tf32(bufB[kb * 136 + nb]);
                    b[nt][1] = f2tf32(bufB[(kb + 4) * 136 + nb]);
                }
            }
#pragma unroll
            for (int mt = 0; mt < 2; mt++)
#pragma unroll
                for (int nt = 0; nt < 8; nt++)
                    mma_tf32(acc[mt][nt], a[mt], b[nt]);
        }
        __syncthreads();
    }

    // ---- epilogue: per-fragment float2 stores ----
#pragma unroll
    for (int mt = 0; mt < 2; mt++) {
        long long r = m0 + warp_m * 32 + mt * 16 + (lane >> 2);
#pragma unroll
        for (int nt = 0; nt < 8; nt++) {
            int c = n0 + warp_n * 64 + nt * 8 + (lane & 3) * 2;
            *reinterpret_cast<float2*>(&C[r * ldc + c]) =
                make_float2(acc[mt][nt][0], acc[mt][nt][1]);
            *reinterpret_cast<float2*>(&C[(r + 8) * ldc + c]) =
                make_float2(acc[mt][nt][2], acc[mt][nt][3]);
        }
    }
}

// ---------------- causal softmax (in place) ---------------------------------
__global__ __launch_bounds__(256) void softmax_causal(float* __restrict__ Sc, int S, float scale)
{
    const int r = blockIdx.x;
    const int b = r / S;
    const int s = r % S;
    float* row = Sc + (long long)b * S * S + (long long)s * S;
    const int L = s + 1;
    const int tid = threadIdx.x;
    __shared__ float red[256];

    float mx = -1e30f;
    for (int i = tid; i < L; i += 256) mx = fmaxf(mx, row[i]);
    red[tid] = mx;
    __syncthreads();
    for (int o = 128; o > 0; o >>= 1) {
        if (tid < o) red[tid] = fmaxf(red[tid], red[tid + o]);
        __syncthreads();
    }
    mx = red[0] * scale;
    __syncthreads();

    float sum = 0.f;
    for (int i = tid; i < L; i += 256) {
        float e = __expf(row[i] * scale - mx);
        row[i] = e;
        sum += e;
    }
    red[tid] = sum;
    __syncthreads();
    for (int o = 128; o > 0; o >>= 1) {
        if (tid < o) red[tid] += red[tid + o];
        __syncthreads();
    }
    const float inv = 1.f / red[0];

    const int Lpad = ((L + 127) / 128) * 128;   // zero diag-block tail
    for (int i = tid; i < Lpad; i += 256) {
        if (i < L) row[i] *= inv;
        else       row[i] = 0.f;
    }
}

// ---------------- driver ----------------------------------------------------
extern "C" void kernel_launch(void* const* d_in, const int* in_sizes, int n_in,
                              void* d_out, int out_size)
{
    const float* x  = (const float*)d_in[0];
    const float* Wq = (const float*)d_in[1];
    const float* Wk = (const float*)d_in[2];
    const float* Wv = (const float*)d_in[3];
    float* out = (float*)d_out;

    float *q, *k, *v, *sc;
    cudaGetSymbolAddress((void**)&q,  g_q);
    cudaGetSymbolAddress((void**)&k,  g_k);
    cudaGetSymbolAddress((void**)&v,  g_v);
    cudaGetSymbolAddress((void**)&sc, g_s);

    cudaFuncSetAttribute(gemm_tc<0,0>, cudaFuncAttributeMaxDynamicSharedMemorySize, SMEM_TOTAL);
    cudaFuncSetAttribute(gemm_tc<1,1>, cudaFuncAttributeMaxDynamicSharedMemorySize, SMEM_TOTAL);
    cudaFuncSetAttribute(gemm_tc<0,2>, cudaFuncAttributeMaxDynamicSharedMemorySize, SMEM_TOTAL);

    const long long sSP  = (long long)SS * PP;
    const long long sSSq = (long long)SS * SS;

    // 1) projections: NN (B*S, D) @ (D, P)
    dim3 gp(PP / 128, (BB * SS) / 128, 1);
    gemm_tc<0,0><<<gp, 256, SMEM_TOTAL>>>(x, Wq, q, DD, PP, PP, DD, 0, 0, 0);
    gemm_tc<0,0><<<gp, 256, SMEM_TOTAL>>>(x, Wk, k, DD, PP, PP, DD, 0, 0, 0);
    gemm_tc<0,0><<<gp, 256, SMEM_TOTAL>>>(x, Wv, v, DD, PP, PP, DD, 0, 0, 0);

    // 2) scores: NT per batch, causal tile skip
    dim3 gs(SS / 128, SS / 128, BB);
    gemm_tc<1,1><<<gs, 256, SMEM_TOTAL>>>(q, k, sc, PP, PP, SS, PP, sSP, sSP, sSSq);

    // 3) softmax (scale 1/sqrt(1024) = 1/32)
    softmax_causal<<<BB * SS, 256>>>(sc, SS, 0.03125f);

    // 4) context: NN per batch, K bounded at diagonal block
    dim3 gc(PP / 128, SS / 128, BB);
    gemm_tc<0,2><<<gc, 256, SMEM_TOTAL>>>(sc, v, out, SS, PP, PP, SS, sSSq, sSP, sSP);
}

// round 7
// speedup vs baseline: 3.7631x; 1.0927x over previous
#include <cuda_runtime.h>
#include <cstdint>

#define BB 4
#define SS 2048
#define DD 1024
#define PP 1024

// ---------------- scratch (device globals; no allocation allowed) ----------
__device__ float g_q [(size_t)BB * SS * PP];           // (B*S, P) tf32-rounded
__device__ float g_k [(size_t)BB * SS * PP];
__device__ float g_v [(size_t)BB * SS * PP];
__device__ float g_s [(size_t)BB * SS * SS];           // scores / probs
__device__ float g_xr[(size_t)BB * SS * DD];           // x tf32-rounded
__device__ float g_wr[3][(size_t)DD * PP];             // W tf32-rounded

// ---------------- helpers ---------------------------------------------------
__device__ __forceinline__ uint32_t smem_u32(const void* p) {
    uint32_t a;
    asm("{ .reg .u64 t; cvta.to.shared.u64 t, %1; cvt.u32.u64 %0, t; }"
        : "=r"(a) : "l"(p));
    return a;
}

__device__ __forceinline__ float f2tf32f(float x) {
    uint32_t r;
    asm("cvt.rna.tf32.f32 %0, %1;" : "=r"(r) : "f"(x));
    return __uint_as_float(r);
}

#define CP_ASYNC16(dst_u32, src_ptr) \
    asm volatile("cp.async.cg.shared.global [%0], [%1], 16;" \
                 :: "r"(dst_u32), "l"(src_ptr) : "memory")
#define CP_COMMIT() asm volatile("cp.async.commit_group;" ::: "memory")
#define CP_WAIT(n)  asm volatile("cp.async.wait_group %0;" :: "n"(n) : "memory")

__device__ __forceinline__ void mma_tf32(float* c, const uint32_t* a, const uint32_t* b) {
    asm volatile(
        "mma.sync.aligned.m16n8k8.row.col.f32.tf32.tf32.f32 "
        "{%0,%1,%2,%3}, {%4,%5,%6,%7}, {%8,%9}, {%0,%1,%2,%3};"
        : "+f"(c[0]), "+f"(c[1]), "+f"(c[2]), "+f"(c[3])
        : "r"(a[0]), "r"(a[1]), "r"(a[2]), "r"(a[3]), "r"(b[0]), "r"(b[1]));
}

// ---------------- tf32 pre-round pass ---------------------------------------
__global__ __launch_bounds__(256) void round_tf32(
    const float* __restrict__ in, float* __restrict__ out, int n4)
{
    int i = blockIdx.x * 256 + threadIdx.x;
    if (i >= n4) return;
    float4 v = reinterpret_cast<const float4*>(in)[i];
    v.x = f2tf32f(v.x); v.y = f2tf32f(v.y);
    v.z = f2tf32f(v.z); v.w = f2tf32f(v.w);
    reinterpret_cast<float4*>(out)[i] = v;
}

// ---------------- tf32 mma.sync GEMM ----------------------------------------
// C[m,n] = sum_k A[m,k] * B_eff[k,n]; inputs already tf32-rounded in GMEM.
//   BT=1 : B stored [N,K] (NT)   BT=0 : B stored [K,N] (NN)
// MODE: 0 plain | 1 causal tile-skip | 2 K bounded at m0+128
// ROUND: round outputs to tf32 on store (for q,k,v)
#define BK 32
#define ASZ 18432            // 128 * 36 * 4
#define BSZ_NT 18432
#define BSZ_NN 17408         // 32 * 136 * 4
#define SMEM_TOTAL 73728

template <int BT, int MODE, int ROUND>
__global__ void __launch_bounds__(256, 2) gemm_tc(
    const float* __restrict__ A, const float* __restrict__ B, float* __restrict__ C,
    int lda, int ldb, int ldc, int K,
    long long sA, long long sB, long long sC)
{
    const int m0 = blockIdx.y * 128;
    const int n0 = blockIdx.x * 128;
    if (MODE == 1 && n0 > m0) return;

    extern __shared__ char smem[];
    const int bz = blockIdx.z;
    A += (long long)bz * sA;
    B += (long long)bz * sB;
    C += (long long)bz * sC;

    const int tid = threadIdx.x;
    const int lane = tid & 31;
    const int wid = tid >> 5;
    const int warp_m = wid & 3;
    const int warp_n = wid >> 2;

    const int BSZ = BT ? BSZ_NT : BSZ_NN;
    const uint32_t* smA = reinterpret_cast<const uint32_t*>(smem);
    const uint32_t* smB = reinterpret_cast<const uint32_t*>(smem + 2 * ASZ);
    const uint32_t smA_u = smem_u32(smA);
    const uint32_t smB_u = smem_u32(smB);

    int kend = K;
    if (MODE == 2) { int lim = m0 + 128; kend = (lim < K) ? lim : K; }
    const int T = kend / BK;

    float acc[2][8][4];
#pragma unroll
    for (int mt = 0; mt < 2; mt++)
#pragma unroll
        for (int nt = 0; nt < 8; nt++)
#pragma unroll
            for (int i = 0; i < 4; i++) acc[mt][nt][i] = 0.f;

    auto load_tile = [&](int kt) {
        const int k0 = kt * BK;
        const int buf = kt & 1;
        const uint32_t dA = smA_u + buf * ASZ;
        const uint32_t dB = smB_u + buf * BSZ;
#pragma unroll
        for (int i = 0; i < 4; i++) {
            int slot = tid + i * 256;
            int row = slot >> 3, c4 = slot & 7;
            const float* srcA = &A[(long long)(m0 + row) * lda + k0 + c4 * 4];
            CP_ASYNC16(dA + (uint32_t)(row * 36 + c4 * 4) * 4u, srcA);
            if (BT) {
                const float* srcB = &B[(long long)(n0 + row) * ldb + k0 + c4 * 4];
                CP_ASYNC16(dB + (uint32_t)(row * 36 + c4 * 4) * 4u, srcB);
            } else {
                int krow = slot >> 5, cc = slot & 31;
                const float* srcB = &B[(long long)(k0 + krow) * ldb + n0 + cc * 4];
                CP_ASYNC16(dB + (uint32_t)(krow * 136 + cc * 4) * 4u, srcB);
            }
        }
        CP_COMMIT();
    };

    load_tile(0);

    const int r0 = warp_m * 32 + (lane >> 2);
    const int cq = lane & 3;

    for (int kt = 0; kt < T; kt++) {
        if (kt + 1 < T) { load_tile(kt + 1); CP_WAIT(1); }
        else            { CP_WAIT(0); }
        __syncthreads();

        const uint32_t* bufA = smA + (kt & 1) * (ASZ / 4);
        const uint32_t* bufB = smB + (kt & 1) * (BSZ / 4);

#pragma unroll
        for (int ks = 0; ks < BK; ks += 8) {
            uint32_t a[2][4];
#pragma unroll
            for (int mt = 0; mt < 2; mt++) {
                int r = r0 + mt * 16;
                int c = ks + cq;
                a[mt][0] = bufA[r * 36 + c];
                a[mt][1] = bufA[(r + 8) * 36 + c];
                a[mt][2] = bufA[r * 36 + c + 4];
                a[mt][3] = bufA[(r + 8) * 36 + c + 4];
            }
            uint32_t b[8][2];
#pragma unroll
            for (int nt = 0; nt < 8; nt++) {
                int nb = warp_n * 64 + nt * 8 + (lane >> 2);
                if (BT) {
                    int c = ks + cq;
                    b[nt][0] = bufB[nb * 36 + c];
                    b[nt][1] = bufB[nb * 36 + c + 4];
                } else {
                    int kb = ks + cq;
                    b[nt][0] = bufB[kb * 136 + nb];
                    b[nt][1] = bufB[(kb + 4) * 136 + nb];
                }
            }
#pragma unroll
            for (int mt = 0; mt < 2; mt++)
#pragma unroll
                for (int nt = 0; nt < 8; nt++)
                    mma_tf32(acc[mt][nt], a[mt], b[nt]);
        }
        __syncthreads();
    }

#pragma unroll
    for (int mt = 0; mt < 2; mt++) {
        long long r = m0 + warp_m * 32 + mt * 16 + (lane >> 2);
#pragma unroll
        for (int nt = 0; nt < 8; nt++) {
            int c = n0 + warp_n * 64 + nt * 8 + (lane & 3) * 2;
            float4 o = make_float4(acc[mt][nt][0], acc[mt][nt][1],
                                   acc[mt][nt][2], acc[mt][nt][3]);
            if (ROUND) {
                o.x = f2tf32f(o.x); o.y = f2tf32f(o.y);
                o.z = f2tf32f(o.z); o.w = f2tf32f(o.w);
            }
            *reinterpret_cast<float2*>(&C[r * ldc + c])       = make_float2(o.x, o.y);
            *reinterpret_cast<float2*>(&C[(r + 8) * ldc + c]) = make_float2(o.z, o.w);
        }
    }
}

// ---------------- register-resident causal softmax ---------------------------
// One block per row. Row <= 2048 floats -> 8 per thread at 256 threads.
// Single gmem read + single gmem write (tf32-rounded probs, zeroed tail).
__global__ __launch_bounds__(256) void softmax_causal(float* __restrict__ Sc, float scale)
{
    const int r = blockIdx.x;
    const int b = r >> 11;              // / 2048
    const int s = r & 2047;
    float* row = Sc + ((size_t)b * SS + s) * SS;
    const int L = s + 1;
    const int Lpad = (L + 127) & ~127;
    const int tid = threadIdx.x;
    const int lane = tid & 31;
    const int wid = tid >> 5;
    __shared__ float red[8];

    float v[8];
    float mx = -1e30f;
#pragma unroll
    for (int j = 0; j < 2; j++) {
        int base = (tid + 256 * j) * 4;
        if (base < Lpad) {
            float4 t = *reinterpret_cast<const float4*>(row + base);
            v[j*4+0] = t.x; v[j*4+1] = t.y; v[j*4+2] = t.z; v[j*4+3] = t.w;
#pragma unroll
            for (int e = 0; e < 4; e++)
                if (base + e < L) mx = fmaxf(mx, v[j*4+e]);
        }
    }
#pragma unroll
    for (int o = 16; o > 0; o >>= 1)
        mx = fmaxf(mx, __shfl_xor_sync(0xffffffffu, mx, o));
    if (lane == 0) red[wid] = mx;
    __syncthreads();
    if (wid == 0) {
        float m = red[lane & 7];
#pragma unroll
        for (int o = 4; o > 0; o >>= 1)
            m = fmaxf(m, __shfl_xor_sync(0xffffffffu, m, o));
        if (lane == 0) red[0] = m;
    }
    __syncthreads();
    mx = red[0] * scale;

    float sum = 0.f;
#pragma unroll
    for (int j = 0; j < 2; j++) {
        int base = (tid + 256 * j) * 4;
        if (base < Lpad) {
#pragma unroll
            for (int e = 0; e < 4; e++) {
                float ev = (base + e < L) ? __expf(v[j*4+e] * scale - mx) : 0.f;
                v[j*4+e] = ev;
                sum += ev;
            }
        }
    }
#pragma unroll
    for (int o = 16; o > 0; o >>= 1)
        sum += __shfl_xor_sync(0xffffffffu, sum, o);
    __syncthreads();
    if (lane == 0) red[wid] = sum;
    __syncthreads();
    if (wid == 0) {
        float m = red[lane & 7];
#pragma unroll
        for (int o = 4; o > 0; o >>= 1)
            m += __shfl_xor_sync(0xffffffffu, m, o);
        if (lane == 0) red[0] = m;
    }
    __syncthreads();
    const float inv = 1.f / red[0];

#pragma unroll
    for (int j = 0; j < 2; j++) {
        int base = (tid + 256 * j) * 4;
        if (base < Lpad) {
            float4 o4;
            o4.x = f2tf32f(v[j*4+0] * inv);
            o4.y = f2tf32f(v[j*4+1] * inv);
            o4.z = f2tf32f(v[j*4+2] * inv);
            o4.w = f2tf32f(v[j*4+3] * inv);
            *reinterpret_cast<float4*>(row + base) = o4;
        }
    }
}

// ---------------- driver ----------------------------------------------------
extern "C" void kernel_launch(void* const* d_in, const int* in_sizes, int n_in,
                              void* d_out, int out_size)
{
    const float* x  = (const float*)d_in[0];
    const float* Wq = (const float*)d_in[1];
    const float* Wk = (const float*)d_in[2];
    const float* Wv = (const float*)d_in[3];
    float* out = (float*)d_out;

    float *q, *k, *v, *sc, *xr, *wr;
    cudaGetSymbolAddress((void**)&q,  g_q);
    cudaGetSymbolAddress((void**)&k,  g_k);
    cudaGetSymbolAddress((void**)&v,  g_v);
    cudaGetSymbolAddress((void**)&sc, g_s);
    cudaGetSymbolAddress((void**)&xr, g_xr);
    cudaGetSymbolAddress((void**)&wr, g_wr);
    float* wqr = wr;
    float* wkr = wr + (size_t)DD * PP;
    float* wvr = wr + (size_t)2 * DD * PP;

    cudaFuncSetAttribute(gemm_tc<0,0,1>, cudaFuncAttributeMaxDynamicSharedMemorySize, SMEM_TOTAL);
    cudaFuncSetAttribute(gemm_tc<1,1,0>, cudaFuncAttributeMaxDynamicSharedMemorySize, SMEM_TOTAL);
    cudaFuncSetAttribute(gemm_tc<0,2,0>, cudaFuncAttributeMaxDynamicSharedMemorySize, SMEM_TOTAL);

    // 0) pre-round x and W to tf32
    const int xn4 = (BB * SS * DD) / 4;
    const int wn4 = (DD * PP) / 4;
    round_tf32<<<(xn4 + 255) / 256, 256>>>(x, xr, xn4);
    round_tf32<<<(wn4 + 255) / 256, 256>>>(Wq, wqr, wn4);
    round_tf32<<<(wn4 + 255) / 256, 256>>>(Wk, wkr, wn4);
    round_tf32<<<(wn4 + 255) / 256, 256>>>(Wv, wvr, wn4);

    const long long sSP  = (long long)SS * PP;
    const long long sSSq = (long long)SS * SS;

    // 1) projections: NN (B*S, D) @ (D, P), outputs tf32-rounded
    dim3 gp(PP / 128, (BB * SS) / 128, 1);
    gemm_tc<0,0,1><<<gp, 256, SMEM_TOTAL>>>(xr, wqr, q, DD, PP, PP, DD, 0, 0, 0);
    gemm_tc<0,0,1><<<gp, 256, SMEM_TOTAL>>>(xr, wkr, k, DD, PP, PP, DD, 0, 0, 0);
    gemm_tc<0,0,1><<<gp, 256, SMEM_TOTAL>>>(xr, wvr, v, DD, PP, PP, DD, 0, 0, 0);

    // 2) scores: NT per batch, causal tile skip
    dim3 gs(SS / 128, SS / 128, BB);
    gemm_tc<1,1,0><<<gs, 256, SMEM_TOTAL>>>(q, k, sc, PP, PP, SS, PP, sSP, sSP, sSSq);

    // 3) softmax (scale 1/32), writes tf32-rounded probs + zero tail
    softmax_causal<<<BB * SS, 256>>>(sc, 0.03125f);

    // 4) context: NN per batch, K bounded at diagonal block
    dim3 gc(PP / 128, SS / 128, BB);
    gemm_tc<0,2,0><<<gc, 256, SMEM_TOTAL>>>(sc, v, out, SS, PP, PP, SS, sSSq, sSP, sSP);
}

// round 8
// speedup vs baseline: 5.6818x; 1.5099x over previous
#include <cuda_runtime.h>
#include <cuda_fp16.h>
#include <cstdint>

#define BB 4
#define SS 2048
#define DD 1024
#define PP 1024

// ---------------- scratch (device globals; no allocation allowed) ----------
__device__ __half g_qh[(size_t)BB * SS * PP];           // (B*S, P)
__device__ __half g_kh[(size_t)BB * SS * PP];
__device__ __half g_vt[(size_t)BB * PP * SS];           // per-batch (P, S)
__device__ float  g_s [(size_t)BB * SS * SS];           // scores fp32
__device__ __half g_ph[(size_t)BB * SS * SS];           // probs half
__device__ __half g_xh[(size_t)BB * SS * DD];           // x in half
__device__ __half g_wt[3][(size_t)PP * DD];             // Wq^T, Wk^T, Wv^T half

// ---------------- helpers ---------------------------------------------------
__device__ __forceinline__ uint32_t smem_u32(const void* p) {
    uint32_t a;
    asm("{ .reg .u64 t; cvta.to.shared.u64 t, %1; cvt.u32.u64 %0, t; }"
        : "=r"(a) : "l"(p));
    return a;
}

#define CP_ASYNC16(dst_u32, src_ptr) \
    asm volatile("cp.async.cg.shared.global [%0], [%1], 16;" \
                 :: "r"(dst_u32), "l"(src_ptr) : "memory")
#define CP_COMMIT() asm volatile("cp.async.commit_group;" ::: "memory")
#define CP_WAIT(n)  asm volatile("cp.async.wait_group %0;" :: "n"(n) : "memory")

__device__ __forceinline__ void mma_f16(float* c, const uint32_t* a, const uint32_t* b) {
    asm volatile(
        "mma.sync.aligned.m16n8k16.row.col.f32.f16.f16.f32 "
        "{%0,%1,%2,%3}, {%4,%5,%6,%7}, {%8,%9}, {%0,%1,%2,%3};"
        : "+f"(c[0]), "+f"(c[1]), "+f"(c[2]), "+f"(c[3])
        : "r"(a[0]), "r"(a[1]), "r"(a[2]), "r"(a[3]), "r"(b[0]), "r"(b[1]));
}

// ---------------- conversion kernels ----------------------------------------
__global__ __launch_bounds__(256) void f2h(
    const float* __restrict__ in, __half* __restrict__ out, int n4)
{
    int i = blockIdx.x * 256 + threadIdx.x;
    if (i >= n4) return;
    float4 v = reinterpret_cast<const float4*>(in)[i];
    __half2 lo = __floats2half2_rn(v.x, v.y);
    __half2 hi = __floats2half2_rn(v.z, v.w);
    reinterpret_cast<uint2*>(out)[i] =
        make_uint2(*reinterpret_cast<uint32_t*>(&lo), *reinterpret_cast<uint32_t*>(&hi));
}

// (D,P) fp32 -> (P,D) half
__global__ __launch_bounds__(256) void transpose_h(
    const float* __restrict__ in, __half* __restrict__ out)
{
    __shared__ float t[32][33];
    int tx = threadIdx.x, ty = threadIdx.y;
    int x = blockIdx.x * 32 + tx;        // P
    int y = blockIdx.y * 32 + ty;        // D
#pragma unroll
    for (int j = 0; j < 32; j += 8)
        t[ty + j][tx] = in[(size_t)(y + j) * PP + x];
    __syncthreads();
    int x2 = blockIdx.y * 32 + tx;       // D
    int y2 = blockIdx.x * 32 + ty;       // P
#pragma unroll
    for (int j = 0; j < 32; j += 8)
        out[(size_t)(y2 + j) * DD + x2] = __float2half_rn(t[tx][ty + j]);
}

// ---------------- fp16 mma.sync NT GEMM --------------------------------------
// C[m,n] = sum_k A[m,k] * B[n,k]; A,B half [.,K] row-major.
// MODE: 0 plain | 1 causal tile-skip | 2 K bounded at m0+128
// OUTH: 1 -> store half, 0 -> store float
#define BK 32
#define ROWW 20                    // uint32 words per smem row (40 halves, pad)
#define TILESZ 10240               // 128 * 80 bytes
#define SMEM_TOTAL 40960           // 4 tiles (A,B double-buffered)

template <int MODE, int OUTH>
__global__ void __launch_bounds__(256, 2) gemm_nt_h(
    const __half* __restrict__ A, const __half* __restrict__ B, void* __restrict__ Cv,
    int lda, int ldb, int ldc, int K,
    long long sA, long long sB, long long sC)
{
    const int m0 = blockIdx.y * 128;
    const int n0 = blockIdx.x * 128;
    if (MODE == 1 && n0 > m0) return;

    extern __shared__ char smem[];
    const int bz = blockIdx.z;
    A += (long long)bz * sA;
    B += (long long)bz * sB;

    const int tid = threadIdx.x;
    const int lane = tid & 31;
    const int wid = tid >> 5;
    const int warp_m = wid & 3;        // 32 rows each
    const int warp_n = wid >> 2;       // 64 cols each
    const int g = lane >> 2;           // 0..7
    const int t = lane & 3;            // 0..3

    const uint32_t* smA = reinterpret_cast<const uint32_t*>(smem);
    const uint32_t* smB = reinterpret_cast<const uint32_t*>(smem + 2 * TILESZ);
    const uint32_t smA_u = smem_u32(smA);
    const uint32_t smB_u = smem_u32(smB);

    int kend = K;
    if (MODE == 2) { int lim = m0 + 128; kend = (lim < K) ? lim : K; }
    const int T = kend / BK;

    float acc[2][8][4];
#pragma unroll
    for (int mt = 0; mt < 2; mt++)
#pragma unroll
        for (int nt = 0; nt < 8; nt++)
#pragma unroll
            for (int i = 0; i < 4; i++) acc[mt][nt][i] = 0.f;

    auto load_tile = [&](int kt) {
        const int k0 = kt * BK;
        const uint32_t dA = smA_u + (kt & 1) * TILESZ;
        const uint32_t dB = smB_u + (kt & 1) * TILESZ;
#pragma unroll
        for (int i = 0; i < 2; i++) {
            int slot = tid + i * 256;           // 0..511
            int row = slot >> 2, c4 = slot & 3; // 128 rows x 4 16B-chunks
            uint32_t doff = (uint32_t)(row * 80 + c4 * 16);
            CP_ASYNC16(dA + doff, &A[(long long)(m0 + row) * lda + k0 + c4 * 8]);
            CP_ASYNC16(dB + doff, &B[(long long)(n0 + row) * ldb + k0 + c4 * 8]);
        }
        CP_COMMIT();
    };

    load_tile(0);

    for (int kt = 0; kt < T; kt++) {
        if (kt + 1 < T) { load_tile(kt + 1); CP_WAIT(1); }
        else            { CP_WAIT(0); }
        __syncthreads();

        const uint32_t* bufA = smA + (kt & 1) * (TILESZ / 4);
        const uint32_t* bufB = smB + (kt & 1) * (TILESZ / 4);

#pragma unroll
        for (int ks = 0; ks < BK; ks += 16) {
            const int kw = (ks >> 1) + t;
            uint32_t a[2][4];
#pragma unroll
            for (int mt = 0; mt < 2; mt++) {
                const uint32_t* pr = bufA + (warp_m * 32 + mt * 16 + g) * ROWW + kw;
                a[mt][0] = pr[0];
                a[mt][1] = pr[8 * ROWW];
                a[mt][2] = pr[4];
                a[mt][3] = pr[8 * ROWW + 4];
            }
            uint32_t b[8][2];
#pragma unroll
            for (int nt = 0; nt < 8; nt++) {
                const uint32_t* pb = bufB + (warp_n * 64 + nt * 8 + g) * ROWW + kw;
                b[nt][0] = pb[0];
                b[nt][1] = pb[4];
            }
#pragma unroll
            for (int mt = 0; mt < 2; mt++)
#pragma unroll
                for (int nt = 0; nt < 8; nt++)
                    mma_f16(acc[mt][nt], a[mt], b[nt]);
        }
        __syncthreads();
    }

    // ---- epilogue ----
    if (OUTH) {
        __half* C = reinterpret_cast<__half*>(Cv) + (long long)bz * sC;
#pragma unroll
        for (int mt = 0; mt < 2; mt++) {
            long long r = m0 + warp_m * 32 + mt * 16 + g;
#pragma unroll
            for (int nt = 0; nt < 8; nt++) {
                int c = n0 + warp_n * 64 + nt * 8 + t * 2;
                *reinterpret_cast<__half2*>(&C[r * ldc + c]) =
                    __floats2half2_rn(acc[mt][nt][0], acc[mt][nt][1]);
                *reinterpret_cast<__half2*>(&C[(r + 8) * ldc + c]) =
                    __floats2half2_rn(acc[mt][nt][2], acc[mt][nt][3]);
            }
        }
    } else {
        float* C = reinterpret_cast<float*>(Cv) + (long long)bz * sC;
#pragma unroll
        for (int mt = 0; mt < 2; mt++) {
            long long r = m0 + warp_m * 32 + mt * 16 + g;
#pragma unroll
            for (int nt = 0; nt < 8; nt++) {
                int c = n0 + warp_n * 64 + nt * 8 + t * 2;
                *reinterpret_cast<float2*>(&C[r * ldc + c]) =
                    make_float2(acc[mt][nt][0], acc[mt][nt][1]);
                *reinterpret_cast<float2*>(&C[(r + 8) * ldc + c]) =
                    make_float2(acc[mt][nt][2], acc[mt][nt][3]);
            }
        }
    }
}

// ---------------- register-resident causal softmax ---------------------------
// Reads fp32 scores, writes half probs (+ zeroed tail to 128-block boundary).
__global__ __launch_bounds__(256) void softmax_causal(
    const float* __restrict__ Sc, __half* __restrict__ Ph, float scale)
{
    const int r = blockIdx.x;
    const int b = r >> 11;
    const int s = r & 2047;
    const float* row = Sc + ((size_t)b * SS + s) * SS;
    __half* prow = Ph + ((size_t)b * SS + s) * SS;
    const int L = s + 1;
    const int Lpad = (L + 127) & ~127;
    const int tid = threadIdx.x;
    const int lane = tid & 31;
    const int wid = tid >> 5;
    __shared__ float red[8];

    float v[8];
    float mx = -1e30f;
#pragma unroll
    for (int j = 0; j < 2; j++) {
        int base = (tid + 256 * j) * 4;
        if (base < Lpad) {
            float4 tv = *reinterpret_cast<const float4*>(row + base);
            v[j*4+0] = tv.x; v[j*4+1] = tv.y; v[j*4+2] = tv.z; v[j*4+3] = tv.w;
#pragma unroll
            for (int e = 0; e < 4; e++)
                if (base + e < L) mx = fmaxf(mx, v[j*4+e]);
        }
    }
#pragma unroll
    for (int o = 16; o > 0; o >>= 1)
        mx = fmaxf(mx, __shfl_xor_sync(0xffffffffu, mx, o));
    if (lane == 0) red[wid] = mx;
    __syncthreads();
    if (wid == 0) {
        float m = red[lane & 7];
#pragma unroll
        for (int o = 4; o > 0; o >>= 1)
            m = fmaxf(m, __shfl_xor_sync(0xffffffffu, m, o));
        if (lane == 0) red[0] = m;
    }
    __syncthreads();
    mx = red[0] * scale;

    float sum = 0.f;
#pragma unroll
    for (int j = 0; j < 2; j++) {
        int base = (tid + 256 * j) * 4;
        if (base < Lpad) {
#pragma unroll
            for (int e = 0; e < 4; e++) {
                float ev = (base + e < L) ? __expf(v[j*4+e] * scale - mx) : 0.f;
                v[j*4+e] = ev;
                sum += ev;
            }
        }
    }
#pragma unroll
    for (int o = 16; o > 0; o >>= 1)
        sum += __shfl_xor_sync(0xffffffffu, sum, o);
    __syncthreads();
    if (lane == 0) red[wid] = sum;
    __syncthreads();
    if (wid == 0) {
        float m = red[lane & 7];
#pragma unroll
        for (int o = 4; o > 0; o >>= 1)
            m += __shfl_xor_sync(0xffffffffu, m, o);
        if (lane == 0) red[0] = m;
    }
    __syncthreads();
    const float inv = 1.f / red[0];

#pragma unroll
    for (int j = 0; j < 2; j++) {
        int base = (tid + 256 * j) * 4;
        if (base < Lpad) {
            __half2 lo = __floats2half2_rn(v[j*4+0] * inv, v[j*4+1] * inv);
            __half2 hi = __floats2half2_rn(v[j*4+2] * inv, v[j*4+3] * inv);
            *reinterpret_cast<uint2*>(prow + base) =
                make_uint2(*reinterpret_cast<uint32_t*>(&lo),
                           *reinterpret_cast<uint32_t*>(&hi));
        }
    }
}

// ---------------- driver ----------------------------------------------------
extern "C" void kernel_launch(void* const* d_in, const int* in_sizes, int n_in,
                              void* d_out, int out_size)
{
    const float* x  = (const float*)d_in[0];
    const float* Wq = (const float*)d_in[1];
    const float* Wk = (const float*)d_in[2];
    const float* Wv = (const float*)d_in[3];
    float* out = (float*)d_out;

    __half *qh, *kh, *vt, *ph, *xh, *wt;
    float* sc;
    cudaGetSymbolAddress((void**)&qh, g_qh);
    cudaGetSymbolAddress((void**)&kh, g_kh);
    cudaGetSymbolAddress((void**)&vt, g_vt);
    cudaGetSymbolAddress((void**)&sc, g_s);
    cudaGetSymbolAddress((void**)&ph, g_ph);
    cudaGetSymbolAddress((void**)&xh, g_xh);
    cudaGetSymbolAddress((void**)&wt, g_wt);
    __half* wqt = wt;
    __half* wkt = wt + (size_t)PP * DD;
    __half* wvt = wt + (size_t)2 * PP * DD;

    cudaFuncSetAttribute(gemm_nt_h<0,1>, cudaFuncAttributeMaxDynamicSharedMemorySize, SMEM_TOTAL);
    cudaFuncSetAttribute(gemm_nt_h<1,0>, cudaFuncAttributeMaxDynamicSharedMemorySize, SMEM_TOTAL);
    cudaFuncSetAttribute(gemm_nt_h<2,0>, cudaFuncAttributeMaxDynamicSharedMemorySize, SMEM_TOTAL);

    // 0) conversions: x -> half, W -> transposed half
    const int xn4 = (BB * SS * DD) / 4;
    f2h<<<(xn4 + 255) / 256, 256>>>(x, xh, xn4);
    dim3 tb(32, 8), tg(32, 32);
    transpose_h<<<tg, tb>>>(Wq, wqt);
    transpose_h<<<tg, tb>>>(Wk, wkt);
    transpose_h<<<tg, tb>>>(Wv, wvt);

    const long long sSP  = (long long)SS * PP;
    const long long sSD  = (long long)SS * DD;
    const long long sPS  = (long long)PP * SS;
    const long long sSSq = (long long)SS * SS;

    // 1) q, k: NT(xh, W^T)  M=B*S, N=P, K=D
    dim3 gp(PP / 128, (BB * SS) / 128, 1);
    gemm_nt_h<0,1><<<gp, 256, SMEM_TOTAL>>>(xh, wqt, qh, DD, DD, PP, DD, 0, 0, 0);
    gemm_nt_h<0,1><<<gp, 256, SMEM_TOTAL>>>(xh, wkt, kh, DD, DD, PP, DD, 0, 0, 0);

    // 2) v^T per batch: NT(Wv^T, xh_b)  M=P, N=S, K=D
    dim3 gv(SS / 128, PP / 128, BB);
    gemm_nt_h<0,1><<<gv, 256, SMEM_TOTAL>>>(wvt, xh, vt, DD, DD, SS, DD, 0, sSD, sPS);

    // 3) scores: NT(q_b, k_b)  M=S, N=S, K=P, causal skip, fp32 out
    dim3 gs(SS / 128, SS / 128, BB);
    gemm_nt_h<1,0><<<gs, 256, SMEM_TOTAL>>>(qh, kh, sc, PP, PP, SS, PP, sSP, sSP, sSSq);

    // 4) softmax (scale 1/32), half probs + zero tail
    softmax_causal<<<BB * SS, 256>>>(sc, ph, 0.03125f);

    // 5) context: NT(P_b, v^T_b)  M=S, N=P, K=S bounded, fp32 out
    dim3 gc(PP / 128, SS / 128, BB);
    gemm_nt_h<2,0><<<gc, 256, SMEM_TOTAL>>>(ph, vt, out, SS, SS, PP, SS, sSSq, sPS, sSP);
}

// round 9
// speedup vs baseline: 6.0937x; 1.0725x over previous
#include <cuda_runtime.h>
#include <cuda_fp16.h>
#include <cstdint>

#define BB 4
#define SS 2048
#define DD 1024
#define PP 1024

// ---------------- scratch (device globals; no allocation allowed) ----------
__device__ __half g_qh[(size_t)BB * SS * PP];           // (B*S, P)
__device__ __half g_kh[(size_t)BB * SS * PP];
__device__ __half g_vt[(size_t)BB * PP * SS];           // per-batch (P, S)
__device__ float  g_s [(size_t)BB * SS * SS];           // scores fp32
__device__ __half g_ph[(size_t)BB * SS * SS];           // probs half
__device__ __half g_xh[(size_t)BB * SS * DD];           // x in half
__device__ __half g_wt[3][(size_t)PP * DD];             // W^T half

// ---------------- helpers ---------------------------------------------------
__device__ __forceinline__ uint32_t smem_u32(const void* p) {
    uint32_t a;
    asm("{ .reg .u64 t; cvta.to.shared.u64 t, %1; cvt.u32.u64 %0, t; }"
        : "=r"(a) : "l"(p));
    return a;
}

#define CP_ASYNC16(dst_u32, src_ptr) \
    asm volatile("cp.async.cg.shared.global [%0], [%1], 16;" \
                 :: "r"(dst_u32), "l"(src_ptr) : "memory")
#define CP_COMMIT() asm volatile("cp.async.commit_group;" ::: "memory")
#define CP_WAIT(n)  asm volatile("cp.async.wait_group %0;" :: "n"(n) : "memory")

#define LDSM_X4(r0, r1, r2, r3, addr) \
    asm volatile("ldmatrix.sync.aligned.m8n8.x4.shared.b16 {%0,%1,%2,%3}, [%4];" \
                 : "=r"(r0), "=r"(r1), "=r"(r2), "=r"(r3) : "r"(addr))

__device__ __forceinline__ void mma_f16(float* c, const uint32_t* a, const uint32_t* b) {
    asm volatile(
        "mma.sync.aligned.m16n8k16.row.col.f32.f16.f16.f32 "
        "{%0,%1,%2,%3}, {%4,%5,%6,%7}, {%8,%9}, {%0,%1,%2,%3};"
        : "+f"(c[0]), "+f"(c[1]), "+f"(c[2]), "+f"(c[3])
        : "r"(a[0]), "r"(a[1]), "r"(a[2]), "r"(a[3]), "r"(b[0]), "r"(b[1]));
}

// ---------------- conversion kernels ----------------------------------------
__global__ __launch_bounds__(256) void f2h(
    const float* __restrict__ in, __half* __restrict__ out, int n4)
{
    int i = blockIdx.x * 256 + threadIdx.x;
    if (i >= n4) return;
    float4 v = reinterpret_cast<const float4*>(in)[i];
    __half2 lo = __floats2half2_rn(v.x, v.y);
    __half2 hi = __floats2half2_rn(v.z, v.w);
    reinterpret_cast<uint2*>(out)[i] =
        make_uint2(*reinterpret_cast<uint32_t*>(&lo), *reinterpret_cast<uint32_t*>(&hi));
}

// (D,P) fp32 -> (P,D) half
__global__ __launch_bounds__(256) void transpose_h(
    const float* __restrict__ in, __half* __restrict__ out)
{
    __shared__ float t[32][33];
    int tx = threadIdx.x, ty = threadIdx.y;
    int x = blockIdx.x * 32 + tx;
    int y = blockIdx.y * 32 + ty;
#pragma unroll
    for (int j = 0; j < 32; j += 8)
        t[ty + j][tx] = in[(size_t)(y + j) * PP + x];
    __syncthreads();
    int x2 = blockIdx.y * 32 + tx;
    int y2 = blockIdx.x * 32 + ty;
#pragma unroll
    for (int j = 0; j < 32; j += 8)
        out[(size_t)(y2 + j) * DD + x2] = __float2half_rn(t[tx][ty + j]);
}

// ---------------- fp16 mma.sync NT GEMM --------------------------------------
// C[m,n] = sum_k A[m,k] * B[n,k]; A,B half row-major, leading dim in halves.
// MODE: 0 plain | 1 causal tile-skip | 2 K bounded at m0+128
// OUTH: 1 -> store half, 0 -> store float
#define BK 32
#define TILEB 10240            // 128 rows * 80 B (40 halves padded)
#define STAGEB 20480           // A + B
#define SMEM_TOTAL 81920       // 4 stages

template <int MODE, int OUTH>
__global__ void __launch_bounds__(256, 2) gemm_nt_h(
    const __half* __restrict__ A, const __half* __restrict__ B, void* __restrict__ Cv,
    int lda, int ldb, int ldc, int K,
    long long sA, long long sB, long long sC)
{
    const int m0 = blockIdx.y * 128;
    const int n0 = blockIdx.x * 128;
    if (MODE == 1 && n0 > m0) return;

    extern __shared__ char smem[];
    const int bz = blockIdx.z;
    A += (long long)bz * sA;
    B += (long long)bz * sB;

    const int tid = threadIdx.x;
    const int lane = tid & 31;
    const int wid = tid >> 5;
    const int warp_m = wid & 3;        // 32 rows each
    const int warp_n = wid >> 2;       // 64 cols each
    const int g = lane >> 2;           // 0..7
    const int t = lane & 3;            // 0..3

    const uint32_t smb = smem_u32(smem);

    int kend = K;
    if (MODE == 2) { int lim = m0 + 128; kend = (lim < K) ? lim : K; }
    const int T = kend / BK;

    float acc[2][8][4];
#pragma unroll
    for (int mt = 0; mt < 2; mt++)
#pragma unroll
        for (int nt = 0; nt < 8; nt++)
#pragma unroll
            for (int i = 0; i < 4; i++) acc[mt][nt][i] = 0.f;

    // tile loader: stage kt&3; 2 x (A+B) float4 per thread
    const int ldrow = tid >> 2;         // 0..63 (+64 second iter)
    const int ldc4  = tid & 3;
    auto load_tile = [&](int kt) {
        const int k0 = kt * BK;
        const uint32_t dA = smb + (kt & 3) * STAGEB;
        const uint32_t dB = dA + TILEB;
#pragma unroll
        for (int i = 0; i < 2; i++) {
            int row = ldrow + i * 64;
            uint32_t doff = (uint32_t)(row * 80 + ldc4 * 16);
            CP_ASYNC16(dA + doff, &A[(long long)(m0 + row) * lda + k0 + ldc4 * 8]);
            CP_ASYNC16(dB + doff, &B[(long long)(n0 + row) * ldb + k0 + ldc4 * 8]);
        }
    };

    // prologue: stages 0,1,2 (always commit to keep group count uniform)
#pragma unroll
    for (int p = 0; p < 3; p++) { if (p < T) load_tile(p); CP_COMMIT(); }

    // ldmatrix lane addressing (row within 16, 16B chunk select)
    const int lr = lane & 15;
    const int lcb = (lane >> 4) * 16;   // byte offset of k-chunk
    const uint32_t aRow = (uint32_t)((warp_m * 32 + lr) * 80) + lcb;
    const uint32_t bRow = (uint32_t)((warp_n * 64 + lr) * 80) + lcb;

    for (int kt = 0; kt < T; kt++) {
        CP_WAIT(2);                 // groups <= kt complete
        __syncthreads();            // all threads done with stage (kt+3)&3's old use
        if (kt + 3 < T) load_tile(kt + 3);
        CP_COMMIT();

        const uint32_t bufA = smb + (kt & 3) * STAGEB;
        const uint32_t bufB = bufA + TILEB;

#pragma unroll
        for (int ks = 0; ks < BK; ks += 16) {
            uint32_t a[2][4];
#pragma unroll
            for (int mt = 0; mt < 2; mt++)
                LDSM_X4(a[mt][0], a[mt][1], a[mt][2], a[mt][3],
                        bufA + aRow + (uint32_t)(mt * 16 * 80 + ks * 2));
            uint32_t b[8][2];
#pragma unroll
            for (int p = 0; p < 4; p++) {
                uint32_t r0, r1, r2, r3;
                LDSM_X4(r0, r1, r2, r3,
                        bufB + bRow + (uint32_t)(p * 16 * 80 + ks * 2));
                b[2*p][0] = r0; b[2*p+1][0] = r1;
                b[2*p][1] = r2; b[2*p+1][1] = r3;
            }
#pragma unroll
            for (int mt = 0; mt < 2; mt++)
#pragma unroll
                for (int nt = 0; nt < 8; nt++)
                    mma_f16(acc[mt][nt], a[mt], b[nt]);
        }
    }

    // ---- epilogue ----
    if (OUTH) {
        __half* C = reinterpret_cast<__half*>(Cv) + (long long)bz * sC;
#pragma unroll
        for (int mt = 0; mt < 2; mt++) {
            long long r = m0 + warp_m * 32 + mt * 16 + g;
#pragma unroll
            for (int nt = 0; nt < 8; nt++) {
                int c = n0 + warp_n * 64 + nt * 8 + t * 2;
                *reinterpret_cast<__half2*>(&C[r * ldc + c]) =
                    __floats2half2_rn(acc[mt][nt][0], acc[mt][nt][1]);
                *reinterpret_cast<__half2*>(&C[(r + 8) * ldc + c]) =
                    __floats2half2_rn(acc[mt][nt][2], acc[mt][nt][3]);
            }
        }
    } else {
        float* C = reinterpret_cast<float*>(Cv) + (long long)bz * sC;
#pragma unroll
        for (int mt = 0; mt < 2; mt++) {
            long long r = m0 + warp_m * 32 + mt * 16 + g;
#pragma unroll
            for (int nt = 0; nt < 8; nt++) {
                int c = n0 + warp_n * 64 + nt * 8 + t * 2;
                *reinterpret_cast<float2*>(&C[r * ldc + c]) =
                    make_float2(acc[mt][nt][0], acc[mt][nt][1]);
                *reinterpret_cast<float2*>(&C[(r + 8) * ldc + c]) =
                    make_float2(acc[mt][nt][2], acc[mt][nt][3]);
            }
        }
    }
}

// ---------------- register-resident causal softmax ---------------------------
__global__ __launch_bounds__(256) void softmax_causal(
    const float* __restrict__ Sc, __half* __restrict__ Ph, float scale)
{
    const int r = blockIdx.x;
    const int b = r >> 11;
    const int s = r & 2047;
    const float* row = Sc + ((size_t)b * SS + s) * SS;
    __half* prow = Ph + ((size_t)b * SS + s) * SS;
    const int L = s + 1;
    const int Lpad = (L + 127) & ~127;
    const int tid = threadIdx.x;
    const int lane = tid & 31;
    const int wid = tid >> 5;
    __shared__ float red[8];

    float v[8];
    float mx = -1e30f;
#pragma unroll
    for (int j = 0; j < 2; j++) {
        int base = (tid + 256 * j) * 4;
        if (base < Lpad) {
            float4 tv = *reinterpret_cast<const float4*>(row + base);
            v[j*4+0] = tv.x; v[j*4+1] = tv.y; v[j*4+2] = tv.z; v[j*4+3] = tv.w;
#pragma unroll
            for (int e = 0; e < 4; e++)
                if (base + e < L) mx = fmaxf(mx, v[j*4+e]);
        }
    }
#pragma unroll
    for (int o = 16; o > 0; o >>= 1)
        mx = fmaxf(mx, __shfl_xor_sync(0xffffffffu, mx, o));
    if (lane == 0) red[wid] = mx;
    __syncthreads();
    if (wid == 0) {
        float m = red[lane & 7];
#pragma unroll
        for (int o = 4; o > 0; o >>= 1)
            m = fmaxf(m, __shfl_xor_sync(0xffffffffu, m, o));
        if (lane == 0) red[0] = m;
    }
    __syncthreads();
    mx = red[0] * scale;

    float sum = 0.f;
#pragma unroll
    for (int j = 0; j < 2; j++) {
        int base = (tid + 256 * j) * 4;
        if (base < Lpad) {
#pragma unroll
            for (int e = 0; e < 4; e++) {
                float ev = (base + e < L) ? __expf(v[j*4+e] * scale - mx) : 0.f;
                v[j*4+e] = ev;
                sum += ev;
            }
        }
    }
#pragma unroll
    for (int o = 16; o > 0; o >>= 1)
        sum += __shfl_xor_sync(0xffffffffu, sum, o);
    __syncthreads();
    if (lane == 0) red[wid] = sum;
    __syncthreads();
    if (wid == 0) {
        float m = red[lane & 7];
#pragma unroll
        for (int o = 4; o > 0; o >>= 1)
            m += __shfl_xor_sync(0xffffffffu, m, o);
        if (lane == 0) red[0] = m;
    }
    __syncthreads();
    const float inv = 1.f / red[0];

#pragma unroll
    for (int j = 0; j < 2; j++) {
        int base = (tid + 256 * j) * 4;
        if (base < Lpad) {
            __half2 lo = __floats2half2_rn(v[j*4+0] * inv, v[j*4+1] * inv);
            __half2 hi = __floats2half2_rn(v[j*4+2] * inv, v[j*4+3] * inv);
            *reinterpret_cast<uint2*>(prow + base) =
                make_uint2(*reinterpret_cast<uint32_t*>(&lo),
                           *reinterpret_cast<uint32_t*>(&hi));
        }
    }
}

// ---------------- driver ----------------------------------------------------
extern "C" void kernel_launch(void* const* d_in, const int* in_sizes, int n_in,
                              void* d_out, int out_size)
{
    const float* x  = (const float*)d_in[0];
    const float* Wq = (const float*)d_in[1];
    const float* Wk = (const float*)d_in[2];
    const float* Wv = (const float*)d_in[3];
    float* out = (float*)d_out;

    __half *qh, *kh, *vt, *ph, *xh, *wt;
    float* sc;
    cudaGetSymbolAddress((void**)&qh, g_qh);
    cudaGetSymbolAddress((void**)&kh, g_kh);
    cudaGetSymbolAddress((void**)&vt, g_vt);
    cudaGetSymbolAddress((void**)&sc, g_s);
    cudaGetSymbolAddress((void**)&ph, g_ph);
    cudaGetSymbolAddress((void**)&xh, g_xh);
    cudaGetSymbolAddress((void**)&wt, g_wt);
    __half* wqt = wt;
    __half* wkt = wt + (size_t)PP * DD;
    __half* wvt = wt + (size_t)2 * PP * DD;

    cudaFuncSetAttribute(gemm_nt_h<0,1>, cudaFuncAttributeMaxDynamicSharedMemorySize, SMEM_TOTAL);
    cudaFuncSetAttribute(gemm_nt_h<1,0>, cudaFuncAttributeMaxDynamicSharedMemorySize, SMEM_TOTAL);
    cudaFuncSetAttribute(gemm_nt_h<2,0>, cudaFuncAttributeMaxDynamicSharedMemorySize, SMEM_TOTAL);

    // 0) conversions: x -> half, W -> transposed half
    const int xn4 = (BB * SS * DD) / 4;
    f2h<<<(xn4 + 255) / 256, 256>>>(x, xh, xn4);
    dim3 tb(32, 8), tg(32, 32);
    transpose_h<<<tg, tb>>>(Wq, wqt);
    transpose_h<<<tg, tb>>>(Wk, wkt);
    transpose_h<<<tg, tb>>>(Wv, wvt);

    const long long sSP  = (long long)SS * PP;
    const long long sSD  = (long long)SS * DD;
    const long long sPS  = (long long)PP * SS;
    const long long sSSq = (long long)SS * SS;

    // 1) q, k: NT(xh, W^T)  M=B*S, N=P, K=D
    dim3 gp(PP / 128, (BB * SS) / 128, 1);
    gemm_nt_h<0,1><<<gp, 256, SMEM_TOTAL>>>(xh, wqt, qh, DD, DD, PP, DD, 0, 0, 0);
    gemm_nt_h<0,1><<<gp, 256, SMEM_TOTAL>>>(xh, wkt, kh, DD, DD, PP, DD, 0, 0, 0);

    // 2) v^T per batch: NT(Wv^T, xh_b)  M=P, N=S, K=D
    dim3 gv(SS / 128, PP / 128, BB);
    gemm_nt_h<0,1><<<gv, 256, SMEM_TOTAL>>>(wvt, xh, vt, DD, DD, SS, DD, 0, sSD, sPS);

    // 3) scores: NT(q_b, k_b)  M=S, N=S, K=P, causal skip, fp32 out
    dim3 gs(SS / 128, SS / 128, BB);
    gemm_nt_h<1,0><<<gs, 256, SMEM_TOTAL>>>(qh, kh, sc, PP, PP, SS, PP, sSP, sSP, sSSq);

    // 4) softmax (scale 1/32), half probs + zero tail
    softmax_causal<<<BB * SS, 256>>>(sc, ph, 0.03125f);

    // 5) context: NT(P_b, v^T_b)  M=S, N=P, K=S bounded, fp32 out
    dim3 gc(PP / 128, SS / 128, BB);
    gemm_nt_h<2,0><<<gc, 256, SMEM_TOTAL>>>(ph, vt, out, SS, SS, PP, SS, sSSq, sPS, sSP);
}